// round 13
// baseline (speedup 1.0000x reference)
#include <cuda_runtime.h>
#include <cuda_fp16.h>
#include <cstdint>

typedef unsigned int u32;

#define Bn 4
#define Ln 2048
#define Sn 2048
#define Hn 16
#define En 64
#define Dn 64
#define BM 128
#define BN 64
#define NT 256
#define NTILES (Sn / BN)
#define L2E 1.44269504f
#define ONE2 0x3C003C00u
#define QSC 4096.0f
#define QSCI 0.000244140625f

// fp16 tiles: 64 elems * 2B + 16B pad = 144 bytes (conflict-free ldmatrix)
#define PITCH 144
#define QTB (128 * PITCH)       // 18432 (Q hi tile)
#define KTB (64 * PITCH)        // 9216  (K/V tile)
#define K8P 80                  // K8 row pitch (bytes): conflict-free LDS pattern
#define K8B (64 * K8P)          // 5120
#define KVB_SZ (2 * KTB + K8B)  // 23552 per buffer: K, V, K8
#define OFF_QH 0
#define OFF_KV(buf) (QTB + (buf) * KVB_SZ)
#define SMEM_BYTES (QTB + 2 * KVB_SZ)   // 65536

// ---------------- scratch ----------------
__device__ __half   g_Qh [(size_t)Bn * Hn * Ln * En];   // [b,h,l,e] fp16
__device__ uint8_t  g_Ql8[(size_t)Bn * Hn * Ln * En];   // e4m3 of (q - qh)*4096
__device__ __half   g_Kf [(size_t)Bn * Hn * Sn * En];   // [b,h,s,e] fp16
__device__ uint8_t  g_K8 [(size_t)Bn * Hn * Sn * En];   // e4m3 of k
__device__ __half   g_Vf [(size_t)Bn * Hn * Sn * Dn];   // [b,h,s,d] fp16

// ---------------- helpers ----------------
__device__ __forceinline__ u32 smem_u32(const void* p) {
    u32 a;
    asm("{ .reg .u64 t; cvta.to.shared.u64 t, %1; cvt.u32.u64 %0, t; }" : "=r"(a) : "l"(p));
    return a;
}
__device__ __forceinline__ void cpa16(u32 dst, const void* src) {
    asm volatile("cp.async.cg.shared.global [%0], [%1], 16;" :: "r"(dst), "l"(src));
}
__device__ __forceinline__ void cpa_commit() {
    asm volatile("cp.async.commit_group;" ::: "memory");
}
template <int N>
__device__ __forceinline__ void cpa_wait() {
    asm volatile("cp.async.wait_group %0;" :: "n"(N) : "memory");
}
__device__ __forceinline__ void ldsm_x4(u32* r, u32 addr) {
    asm volatile("ldmatrix.sync.aligned.m8n8.x4.shared.b16 {%0,%1,%2,%3}, [%4];"
                 : "=r"(r[0]), "=r"(r[1]), "=r"(r[2]), "=r"(r[3]) : "r"(addr));
}
__device__ __forceinline__ void ldsm_x4_t(u32* r, u32 addr) {
    asm volatile("ldmatrix.sync.aligned.m8n8.x4.trans.shared.b16 {%0,%1,%2,%3}, [%4];"
                 : "=r"(r[0]), "=r"(r[1]), "=r"(r[2]), "=r"(r[3]) : "r"(addr));
}
__device__ __forceinline__ u32 lds32(u32 addr) {
    u32 d;
    asm volatile("ld.shared.b32 %0, [%1];" : "=r"(d) : "r"(addr));
    return d;
}
__device__ __forceinline__ void mma_fp16(float* c, const u32* a, u32 b0, u32 b1) {
    asm volatile(
        "mma.sync.aligned.m16n8k16.row.col.f32.f16.f16.f32 "
        "{%0,%1,%2,%3}, {%4,%5,%6,%7}, {%8,%9}, {%0,%1,%2,%3};"
        : "+f"(c[0]), "+f"(c[1]), "+f"(c[2]), "+f"(c[3])
        : "r"(a[0]), "r"(a[1]), "r"(a[2]), "r"(a[3]), "r"(b0), "r"(b1));
}
__device__ __forceinline__ void mma_e4m3(float* c, const u32* a, u32 b0, u32 b1) {
    asm volatile(
        "mma.sync.aligned.m16n8k32.row.col.f32.e4m3.e4m3.f32 "
        "{%0,%1,%2,%3}, {%4,%5,%6,%7}, {%8,%9}, {%0,%1,%2,%3};"
        : "+f"(c[0]), "+f"(c[1]), "+f"(c[2]), "+f"(c[3])
        : "r"(a[0]), "r"(a[1]), "r"(a[2]), "r"(a[3]), "r"(b0), "r"(b1));
}
__device__ __forceinline__ u32 cvt_f16x2(float lo, float hi) {
    u32 d;
    asm("cvt.rn.f16x2.f32 %0, %1, %2;" : "=r"(d) : "f"(hi), "f"(lo));
    return d;
}
__device__ __forceinline__ u32 ex2_f16x2(u32 x) {
    u32 d;
    asm("ex2.approx.f16x2 %0, %1;" : "=r"(d) : "r"(x));
    return d;
}
__device__ __forceinline__ u32 pack_e4m3_4(float f0, float f1, float f2, float f3) {
    unsigned short lo, hi;
    asm("cvt.rn.satfinite.e4m3x2.f32 %0, %1, %2;" : "=h"(lo) : "f"(f1), "f"(f0));
    asm("cvt.rn.satfinite.e4m3x2.f32 %0, %1, %2;" : "=h"(hi) : "f"(f3), "f"(f2));
    return (u32)lo | ((u32)hi << 16);
}

// ---------------- fused pre-pass: one kernel, 3 regions ----------------
// y=0: Q -> g_Qh (fp16) + g_Ql8 (e4m3 residual*4096)
// y=1: K -> g_Kf (fp16) + g_K8 (e4m3)
// y=2: V -> g_Vf (fp16)
__global__ void pack_all(const float* __restrict__ Q, const float* __restrict__ K,
                         const float* __restrict__ V) {
    const int region = blockIdx.y;
    const int i4 = blockIdx.x * 256 + threadIdx.x;
    const size_t lin = (size_t)i4 * 4;
    const int e = lin & 63;
    const int h = (lin >> 6) & 15;
    const int x = (lin >> 10) & 2047;
    const int b = (int)(lin >> 21);
    const size_t dst = ((((size_t)b * Hn + h) * Ln + x) * En) + e;

    if (region == 0) {
        float4 v = ((const float4*)Q)[i4];
        float xx[4] = {v.x, v.y, v.z, v.w};
        __half hh[4];
        float ql[4];
#pragma unroll
        for (int j = 0; j < 4; ++j) {
            hh[j] = __float2half_rn(xx[j]);
            ql[j] = (xx[j] - __half2float(hh[j])) * QSC;
        }
        *(uint2*)(g_Qh + dst) = *(uint2*)hh;
        *(u32*)(g_Ql8 + dst) = pack_e4m3_4(ql[0], ql[1], ql[2], ql[3]);
    } else if (region == 1) {
        float4 v = ((const float4*)K)[i4];
        __half hh[4] = {__float2half_rn(v.x), __float2half_rn(v.y),
                        __float2half_rn(v.z), __float2half_rn(v.w)};
        *(uint2*)(g_Kf + dst) = *(uint2*)hh;
        *(u32*)(g_K8 + dst) = pack_e4m3_4(v.x, v.y, v.z, v.w);
    } else {
        float4 v = ((const float4*)V)[i4];
        __half hh[4] = {__float2half_rn(v.x), __float2half_rn(v.y),
                        __float2half_rn(v.z), __float2half_rn(v.w)};
        *(uint2*)(g_Vf + dst) = *(uint2*)hh;
    }
}

// ---------------- main attention kernel ----------------
extern __shared__ char dsm[];

__global__ __launch_bounds__(NT, 2)
void fattn_mma(float* __restrict__ O) {
    const u32 sb = smem_u32(dsm);
    const int tid = threadIdx.x;
    const int w = tid >> 5;
    const int lane = tid & 31;
    const int gid8 = lane >> 2;          // fragment group id
    const int c4i = (lane & 3) * 4;      // byte offset within k-groups

    const int bh = blockIdx.y;
    const int b = bh >> 4, h = bh & 15;
    const int mbase = blockIdx.x * BM;

    const __half*   gq_h = g_Qh + ((size_t)bh * Ln + mbase) * En;
    const __half*   gk   = g_Kf + (size_t)bh * Sn * En;
    const uint8_t*  gk8  = g_K8 + (size_t)bh * Sn * En;
    const __half*   gv   = g_Vf + (size_t)bh * Sn * Dn;

    // prologue: Q hi (128 rows) + tile0 K,V,K8
#pragma unroll
    for (int i = 0; i < 4; ++i) {
        int idx = tid + i * NT;
        u32 d = sb + (idx >> 3) * PITCH + (idx & 7) * 16;
        cpa16(d + OFF_QH, (const char*)gq_h + idx * 16);
    }
#pragma unroll
    for (int i = 0; i < 2; ++i) {
        int idx = tid + i * NT;
        u32 d = sb + OFF_KV(0) + (idx >> 3) * PITCH + (idx & 7) * 16;
        cpa16(d + 0 * KTB, (const char*)gk + idx * 16);
        cpa16(d + 1 * KTB, (const char*)gv + idx * 16);
    }
    cpa16(sb + OFF_KV(0) + 2 * KTB + (tid >> 2) * K8P + (tid & 3) * 16,
          (const char*)gk8 + tid * 16);
    cpa_commit();

    // persistent fp8 Ql fragments (m16n8k32 A layout), direct from global
    u32 A8[2][4];
    {
        const uint8_t* gq8 = g_Ql8 + ((size_t)bh * Ln + mbase + 16 * w) * En;
#pragma unroll
        for (int hf = 0; hf < 2; ++hf) {
            const uint8_t* p = gq8 + c4i + 32 * hf;
            A8[hf][0] = *(const u32*)(p + gid8 * 64);
            A8[hf][1] = *(const u32*)(p + (gid8 + 8) * 64);
            A8[hf][2] = *(const u32*)(p + gid8 * 64 + 16);
            A8[hf][3] = *(const u32*)(p + (gid8 + 8) * 64 + 16);
        }
    }

    const u32 koff = (lane & 7) * PITCH + (lane >> 3) * 16;
    const u32 qoff = (16 * w + ((lane >> 3) & 1) * 8 + (lane & 7)) * PITCH + (lane >> 4) * 16;
    const u32 voff = (((lane >> 3) & 1) * 8 + (lane & 7)) * PITCH + (lane >> 4) * 16;

    u32 Qh[4][4];                      // persistent fp16 Q hi fragments
    float accO[8][4];
#pragma unroll
    for (int j = 0; j < 8; ++j)
#pragma unroll
        for (int i = 0; i < 4; ++i) accO[j][i] = 0.f;
    float accL[4] = {0.f, 0.f, 0.f, 0.f};
    float m0 = -1e30f, m1 = -1e30f;

    for (int t = 0; t < NTILES; ++t) {
        const u32 kvb = sb + OFF_KV(t & 1);

        cpa_wait<0>();
        __syncthreads();      // data visible + prev buffer free

        if (t + 1 < NTILES) {
            const u32 nb = sb + OFF_KV((t + 1) & 1);
            const size_t goffK = (size_t)(t + 1) * BN * En;
            const size_t goffV = (size_t)(t + 1) * BN * Dn;
#pragma unroll
            for (int i = 0; i < 2; ++i) {
                int idx = tid + i * NT;
                u32 d = nb + (idx >> 3) * PITCH + (idx & 7) * 16;
                cpa16(d + 0 * KTB, (const char*)(gk + goffK) + idx * 16);
                cpa16(d + 1 * KTB, (const char*)(gv + goffV) + idx * 16);
            }
            cpa16(nb + 2 * KTB + (tid >> 2) * K8P + (tid & 3) * 16,
                  (const char*)(gk8 + goffK) + tid * 16);
            cpa_commit();
        }

        if (t == 0) {
#pragma unroll
            for (int k = 0; k < 4; ++k) ldsm_x4(Qh[k], sb + OFF_QH + k * 32 + qoff);
        }

        // ---- S main term: Qh*K (fp16), software-pipelined K fragments ----
        float accS[8][4];
#pragma unroll
        for (int j = 0; j < 8; ++j)
#pragma unroll
            for (int i = 0; i < 4; ++i) accS[j][i] = 0.f;

        {
            const u32 kbase = kvb + koff;
            u32 kc[4], kn[4];
            ldsm_x4(kc, kbase);
#pragma unroll
            for (int idx = 0; idx < 16; ++idx) {
                const int hh = idx >> 3, j = idx & 7;
                if (idx < 15) {
                    const int n = idx + 1;
                    ldsm_x4(kn, kbase + (n & 7) * (8 * PITCH) + (n >> 3) * 64);
                }
                mma_fp16(accS[j], Qh[2 * hh],     kc[0], kc[1]);
                mma_fp16(accS[j], Qh[2 * hh + 1], kc[2], kc[3]);
                kc[0] = kn[0]; kc[1] = kn[1]; kc[2] = kn[2]; kc[3] = kn[3];
            }
        }

        // ---- S correction: (Ql8 * K8) * 2^-12 via fp8 m16n8k32 ----
        {
            const u32 k8base = kvb + 2 * KTB + gid8 * K8P + c4i;
#pragma unroll
            for (int j = 0; j < 8; ++j) {
                const u32 kb = k8base + j * (8 * K8P);
                u32 b00 = lds32(kb),      b01 = lds32(kb + 16);
                u32 b10 = lds32(kb + 32), b11 = lds32(kb + 48);
                float c4[4] = {0.f, 0.f, 0.f, 0.f};
                mma_e4m3(c4, A8[0], b00, b01);
                mma_e4m3(c4, A8[1], b10, b11);
                accS[j][0] = fmaf(QSCI, c4[0], accS[j][0]);
                accS[j][1] = fmaf(QSCI, c4[1], accS[j][1]);
                accS[j][2] = fmaf(QSCI, c4[2], accS[j][2]);
                accS[j][3] = fmaf(QSCI, c4[3], accS[j][3]);
            }
        }

        // ---- online softmax: tile row max, rescale (R7 form) ----
        float tm0 = accS[0][0], tm1 = accS[0][2];
#pragma unroll
        for (int j = 0; j < 8; ++j) {
            tm0 = fmaxf(tm0, fmaxf(accS[j][0], accS[j][1]));
            tm1 = fmaxf(tm1, fmaxf(accS[j][2], accS[j][3]));
        }
        tm0 = fmaxf(tm0, __shfl_xor_sync(0xffffffffu, tm0, 1));
        tm1 = fmaxf(tm1, __shfl_xor_sync(0xffffffffu, tm1, 1));
        tm0 = fmaxf(tm0, __shfl_xor_sync(0xffffffffu, tm0, 2));
        tm1 = fmaxf(tm1, __shfl_xor_sync(0xffffffffu, tm1, 2));

        const u32 vbase = kvb + 1 * KTB + voff;
        u32 vc[4], vn[4];
        ldsm_x4_t(vc, vbase);    // first V fragment overlaps the ALU below

        const float nm0 = fmaxf(m0, tm0);
        const float nm1 = fmaxf(m1, tm1);
        const float al0 = __expf(m0 - nm0);
        const float al1 = __expf(m1 - nm1);
        m0 = nm0; m1 = nm1;
        const float c0 = -nm0 * L2E;
        const float c1 = -nm1 * L2E;

#pragma unroll
        for (int j = 0; j < 8; ++j) {
            accO[j][0] *= al0; accO[j][1] *= al0;
            accO[j][2] *= al1; accO[j][3] *= al1;
        }
        accL[0] *= al0;
        accL[2] *= al1;

        // ---- PV: per kt convert to fp16 P, then MMAs with pipelined V fragments ----
#pragma unroll
        for (int idx = 0; idx < 16; ++idx) {
            const int kt = idx >> 2, q = idx & 3;
            u32 ah[4];
            if (q == 0) {
                ah[0] = ex2_f16x2(cvt_f16x2(fmaf(accS[2 * kt][0], L2E, c0),
                                            fmaf(accS[2 * kt][1], L2E, c0)));
                ah[1] = ex2_f16x2(cvt_f16x2(fmaf(accS[2 * kt][2], L2E, c1),
                                            fmaf(accS[2 * kt][3], L2E, c1)));
                ah[2] = ex2_f16x2(cvt_f16x2(fmaf(accS[2 * kt + 1][0], L2E, c0),
                                            fmaf(accS[2 * kt + 1][1], L2E, c0)));
                ah[3] = ex2_f16x2(cvt_f16x2(fmaf(accS[2 * kt + 1][2], L2E, c1),
                                            fmaf(accS[2 * kt + 1][3], L2E, c1)));
                accS[2 * kt][0] = __uint_as_float(ah[0]);
                accS[2 * kt][1] = __uint_as_float(ah[1]);
                accS[2 * kt][2] = __uint_as_float(ah[2]);
                accS[2 * kt][3] = __uint_as_float(ah[3]);
                mma_fp16(accL, ah, ONE2, ONE2);   // row sums via tensor pipe
            } else {
                ah[0] = __float_as_uint(accS[2 * kt][0]);
                ah[1] = __float_as_uint(accS[2 * kt][1]);
                ah[2] = __float_as_uint(accS[2 * kt][2]);
                ah[3] = __float_as_uint(accS[2 * kt][3]);
            }
            if (idx < 15) {
                const int n = idx + 1;
                ldsm_x4_t(vn, vbase + (n >> 2) * (16 * PITCH) + (n & 3) * 32);
            }
            mma_fp16(accO[2 * q],     ah, vc[0], vc[1]);
            mma_fp16(accO[2 * q + 1], ah, vc[2], vc[3]);
            vc[0] = vn[0]; vc[1] = vn[1]; vc[2] = vn[2]; vc[3] = vn[3];
        }
    }

    // ---- epilogue: l exact from the ones-MMA ----
    const float inv0 = 1.f / accL[0];
    const float inv1 = 1.f / accL[2];

    const int row0 = mbase + 16 * w + (lane >> 2);
    float* o0 = O + (((size_t)b * Ln + row0) * Hn + h) * Dn + (lane & 3) * 2;
    float* o1 = o0 + (size_t)8 * Hn * Dn;
#pragma unroll
    for (int j = 0; j < 8; ++j) {
        *(float2*)(o0 + 8 * j) = make_float2(accO[j][0] * inv0, accO[j][1] * inv0);
        *(float2*)(o1 + 8 * j) = make_float2(accO[j][2] * inv1, accO[j][3] * inv1);
    }
}

// ---------------- launch ----------------
extern "C" void kernel_launch(void* const* d_in, const int* in_sizes, int n_in,
                              void* d_out, int out_size) {
    const float* Q = (const float*)d_in[0];
    const float* K = (const float*)d_in[1];
    const float* V = (const float*)d_in[2];
    float* O = (float*)d_out;

    pack_all<<<dim3(8192, 3), 256>>>(Q, K, V);

    cudaFuncSetAttribute(fattn_mma, cudaFuncAttributeMaxDynamicSharedMemorySize, SMEM_BYTES);
    fattn_mma<<<dim3(Ln / BM, Bn * Hn), NT, SMEM_BYTES>>>(O);
}

// round 17
// speedup vs baseline: 1.2987x; 1.2987x over previous
#include <cuda_runtime.h>
#include <cuda_fp16.h>
#include <cstdint>

typedef unsigned int u32;

#define Bn 4
#define Ln 2048
#define Sn 2048
#define Hn 16
#define En 64
#define Dn 64
#define BM 128
#define BN 64
#define NT 256
#define NTILES (Sn / BN)
#define L2E 1.44269504f
#define ONE2 0x3C003C00u

// pitch: 64 elems * 2B + 16B pad = 144 bytes (conflict-free ldmatrix)
#define PITCH 144
#define QTB (128 * PITCH)     // 18432 (Q tile: 128 rows)
#define KTB (64 * PITCH)      // 9216  (K/V tile: 64 rows)
#define NSLOT 3
#define OFF_QH 0
#define OFF_QL (OFF_QH + QTB)
#define OFF_KV(s) (2 * QTB + (s) * 2 * KTB)
#define OFF_MB (2 * QTB + NSLOT * 2 * KTB)          // 92160
#define SMEM_BYTES (OFF_MB + 64)                    // 92224

#define MB_FULL(s)  (sb + OFF_MB + (s) * 16)
#define MB_EMPTY(s) (sb + OFF_MB + (s) * 16 + 8)

// ---------------- scratch (fp16, repacked [b,h,s,e]) ----------------
__device__ __half g_Qh[(size_t)Bn * Hn * Ln * En];
__device__ __half g_Ql[(size_t)Bn * Hn * Ln * En];
__device__ __half g_Kf[(size_t)Bn * Hn * Sn * En];
__device__ __half g_Vf[(size_t)Bn * Hn * Sn * Dn];

// ---------------- helpers ----------------
__device__ __forceinline__ u32 smem_u32(const void* p) {
    u32 a;
    asm("{ .reg .u64 t; cvta.to.shared.u64 t, %1; cvt.u32.u64 %0, t; }" : "=r"(a) : "l"(p));
    return a;
}
__device__ __forceinline__ void cpa16(u32 dst, const void* src) {
    asm volatile("cp.async.cg.shared.global [%0], [%1], 16;" :: "r"(dst), "l"(src));
}
__device__ __forceinline__ void ldsm_x4(u32* r, u32 addr) {
    asm volatile("ldmatrix.sync.aligned.m8n8.x4.shared.b16 {%0,%1,%2,%3}, [%4];"
                 : "=r"(r[0]), "=r"(r[1]), "=r"(r[2]), "=r"(r[3]) : "r"(addr));
}
__device__ __forceinline__ void ldsm_x4_t(u32* r, u32 addr) {
    asm volatile("ldmatrix.sync.aligned.m8n8.x4.trans.shared.b16 {%0,%1,%2,%3}, [%4];"
                 : "=r"(r[0]), "=r"(r[1]), "=r"(r[2]), "=r"(r[3]) : "r"(addr));
}
__device__ __forceinline__ void mma_fp16(float* c, const u32* a, u32 b0, u32 b1) {
    asm volatile(
        "mma.sync.aligned.m16n8k16.row.col.f32.f16.f16.f32 "
        "{%0,%1,%2,%3}, {%4,%5,%6,%7}, {%8,%9}, {%0,%1,%2,%3};"
        : "+f"(c[0]), "+f"(c[1]), "+f"(c[2]), "+f"(c[3])
        : "r"(a[0]), "r"(a[1]), "r"(a[2]), "r"(a[3]), "r"(b0), "r"(b1));
}
__device__ __forceinline__ u32 cvt_f16x2(float lo, float hi) {
    u32 d;
    asm("cvt.rn.f16x2.f32 %0, %1, %2;" : "=r"(d) : "f"(hi), "f"(lo));
    return d;
}
__device__ __forceinline__ u32 ex2_f16x2(u32 x) {
    u32 d;
    asm("ex2.approx.f16x2 %0, %1;" : "=r"(d) : "r"(x));
    return d;
}

#define MBARRIER_INIT(addr, cnt) \
    asm volatile("mbarrier.init.shared.b64 [%0], %1;" :: "r"((u32)(addr)), "r"((u32)(cnt)) : "memory")
#define MBARRIER_ARRIVE(addr) \
    asm volatile("mbarrier.arrive.shared.b64 _, [%0];" :: "r"((u32)(addr)) : "memory")
// .noinc is load-bearing: the async completion must CONSUME one of the expected
// arrivals (the default variant pre-increments the count and is net-zero -> hang).
#define CPA_MBAR_ARRIVE(addr) \
    asm volatile("cp.async.mbarrier.arrive.noinc.shared.b64 [%0];" :: "r"((u32)(addr)) : "memory")

#define MBARRIER_WAIT_PARITY(addr, parity) do {                                              \
    u32 _m = (u32)(addr); u32 _p = (u32)(parity); u32 _done;                                 \
    asm volatile("{\n\t.reg .pred p;\n\t"                                                    \
        "mbarrier.try_wait.parity.acquire.cta.shared::cta.b64 p, [%1], %2;\n\t"              \
        "selp.b32 %0, 1, 0, p;\n\t}" : "=r"(_done) : "r"(_m), "r"(_p) : "memory");           \
    if (!_done) {                                                                            \
        asm volatile("{\n\t.reg .pred P1;\n\t"                                               \
            "WL_%=:\n\t"                                                                     \
            "mbarrier.try_wait.parity.acquire.cta.shared::cta.b64 P1, [%0], %1, 0x989680;\n\t" \
            "@P1 bra.uni WD_%=;\n\t"                                                         \
            "bra.uni WL_%=;\n\t"                                                             \
            "WD_%=:\n\t}" :: "r"(_m), "r"(_p) : "memory");                                   \
    }                                                                                        \
} while (0)

// ---------------- fused pre-pass: one kernel, 3 regions ----------------
__global__ void pack_all(const float* __restrict__ Q, const float* __restrict__ K,
                         const float* __restrict__ V) {
    const int region = blockIdx.y;
    const int i4 = blockIdx.x * 256 + threadIdx.x;
    const size_t lin = (size_t)i4 * 4;
    const int e = lin & 63;
    const int h = (lin >> 6) & 15;
    const int x = (lin >> 10) & 2047;
    const int b = (int)(lin >> 21);
    const size_t dst = ((((size_t)b * Hn + h) * Ln + x) * En) + e;

    if (region == 0) {
        float4 v = ((const float4*)Q)[i4];
        float xx[4] = {v.x, v.y, v.z, v.w};
        __half hh[4], ll[4];
#pragma unroll
        for (int j = 0; j < 4; ++j) {
            hh[j] = __float2half_rn(xx[j]);
            ll[j] = __float2half_rn(xx[j] - __half2float(hh[j]));
        }
        *(uint2*)(g_Qh + dst) = *(uint2*)hh;
        *(uint2*)(g_Ql + dst) = *(uint2*)ll;
    } else {
        const float* src = (region == 1) ? K : V;
        __half* out = (region == 1) ? g_Kf : g_Vf;
        float4 v = ((const float4*)src)[i4];
        __half hh[4] = {__float2half_rn(v.x), __float2half_rn(v.y),
                        __float2half_rn(v.z), __float2half_rn(v.w)};
        *(uint2*)(out + dst) = *(uint2*)hh;
    }
}

// ---------------- main attention kernel ----------------
extern __shared__ char dsm[];

__global__ __launch_bounds__(NT, 2)
void fattn_mma(float* __restrict__ O) {
    const u32 sb = smem_u32(dsm);
    const int tid = threadIdx.x;
    const int w = tid >> 5;
    const int lane = tid & 31;

    const int bh = blockIdx.y;
    const int b = bh >> 4, h = bh & 15;
    const int mbase = blockIdx.x * BM;

    const __half* gq_h = g_Qh + ((size_t)bh * Ln + mbase) * En;
    const __half* gq_l = g_Ql + ((size_t)bh * Ln + mbase) * En;
    const __half* gk   = g_Kf + (size_t)bh * Sn * En;
    const __half* gv   = g_Vf + (size_t)bh * Sn * Dn;

    // ---- mbarrier init (full/empty per slot, count = all 256 threads) ----
    if (tid == 0) {
#pragma unroll
        for (int s = 0; s < NSLOT; ++s) {
            MBARRIER_INIT(MB_FULL(s), NT);
            MBARRIER_INIT(MB_EMPTY(s), NT);
        }
    }
    __syncthreads();

    // producer cursor (phase starts at 1 so first empty-waits pass immediately)
    int pstage = 0, pphase = 1;
    // consumer cursor
    int cstage = 0, cphase = 0;

    // ---- prologue: produce slot0 (Q + tile0) and slot1 (tile1) ----
    {
        MBARRIER_WAIT_PARITY(MB_EMPTY(0), 1);
#pragma unroll
        for (int i = 0; i < 4; ++i) {
            int idx = tid + i * NT;
            u32 d = sb + (idx >> 3) * PITCH + (idx & 7) * 16;
            cpa16(d + OFF_QH, (const char*)gq_h + idx * 16);
            cpa16(d + OFF_QL, (const char*)gq_l + idx * 16);
        }
#pragma unroll
        for (int i = 0; i < 2; ++i) {
            int idx = tid + i * NT;
            u32 d = sb + OFF_KV(0) + (idx >> 3) * PITCH + (idx & 7) * 16;
            cpa16(d, (const char*)gk + idx * 16);
            cpa16(d + KTB, (const char*)gv + idx * 16);
        }
        CPA_MBAR_ARRIVE(MB_FULL(0));
        pstage = 1;

        MBARRIER_WAIT_PARITY(MB_EMPTY(1), 1);
#pragma unroll
        for (int i = 0; i < 2; ++i) {
            int idx = tid + i * NT;
            u32 d = sb + OFF_KV(1) + (idx >> 3) * PITCH + (idx & 7) * 16;
            cpa16(d, (const char*)(gk + (size_t)BN * En) + idx * 16);
            cpa16(d + KTB, (const char*)(gv + (size_t)BN * Dn) + idx * 16);
        }
        CPA_MBAR_ARRIVE(MB_FULL(1));
        pstage = 2;
    }

    const u32 koff = (lane & 7) * PITCH + (lane >> 3) * 16;
    const u32 qoff = (16 * w + ((lane >> 3) & 1) * 8 + (lane & 7)) * PITCH + (lane >> 4) * 16;
    const u32 voff = (((lane >> 3) & 1) * 8 + (lane & 7)) * PITCH + (lane >> 4) * 16;

    u32 Qh[4][4], Ql[4][4];            // persistent (tile-invariant)
    float accO[8][4];
#pragma unroll
    for (int j = 0; j < 8; ++j)
#pragma unroll
        for (int i = 0; i < 4; ++i) accO[j][i] = 0.f;
    float accL[4] = {0.f, 0.f, 0.f, 0.f};
    float m0 = -1e30f, m1 = -1e30f;

    for (int t = 0; t < NTILES; ++t) {
        // ---- produce tile t+2 into slot pstage ----
        if (t + 2 < NTILES) {
            MBARRIER_WAIT_PARITY(MB_EMPTY(pstage), pphase);
            const size_t goffK = (size_t)(t + 2) * BN * En;
            const size_t goffV = (size_t)(t + 2) * BN * Dn;
            const u32 nb = sb + OFF_KV(pstage);
#pragma unroll
            for (int i = 0; i < 2; ++i) {
                int idx = tid + i * NT;
                u32 d = nb + (idx >> 3) * PITCH + (idx & 7) * 16;
                cpa16(d, (const char*)(gk + goffK) + idx * 16);
                cpa16(d + KTB, (const char*)(gv + goffV) + idx * 16);
            }
            CPA_MBAR_ARRIVE(MB_FULL(pstage));
            if (++pstage == NSLOT) { pstage = 0; pphase ^= 1; }
        }

        // ---- consume tile t from slot cstage ----
        MBARRIER_WAIT_PARITY(MB_FULL(cstage), cphase);
        const u32 kvb = sb + OFF_KV(cstage);

        if (t == 0) {
#pragma unroll
            for (int k = 0; k < 4; ++k) {
                ldsm_x4(Qh[k], sb + OFF_QH + k * 32 + qoff);
                ldsm_x4(Ql[k], sb + OFF_QL + k * 32 + qoff);
            }
        }

        // ---- S = Qh*K + Ql*K (fp16 2-term), software-pipelined K fragments ----
        float accS[8][4];
#pragma unroll
        for (int j = 0; j < 8; ++j)
#pragma unroll
            for (int i = 0; i < 4; ++i) accS[j][i] = 0.f;

        {
            const u32 kbase = kvb + koff;
            u32 kc[4], kn[4];
            ldsm_x4(kc, kbase);
#pragma unroll
            for (int idx = 0; idx < 16; ++idx) {
                const int hh = idx >> 3, j = idx & 7;
                if (idx < 15) {
                    const int n = idx + 1;
                    ldsm_x4(kn, kbase + (n & 7) * (8 * PITCH) + (n >> 3) * 64);
                }
                mma_fp16(accS[j], Qh[2 * hh],     kc[0], kc[1]);
                mma_fp16(accS[j], Ql[2 * hh],     kc[0], kc[1]);
                mma_fp16(accS[j], Qh[2 * hh + 1], kc[2], kc[3]);
                mma_fp16(accS[j], Ql[2 * hh + 1], kc[2], kc[3]);
                kc[0] = kn[0]; kc[1] = kn[1]; kc[2] = kn[2]; kc[3] = kn[3];
            }
        }

        // ---- online softmax: tile row max, rescale ----
        float tm0 = accS[0][0], tm1 = accS[0][2];
#pragma unroll
        for (int j = 0; j < 8; ++j) {
            tm0 = fmaxf(tm0, fmaxf(accS[j][0], accS[j][1]));
            tm1 = fmaxf(tm1, fmaxf(accS[j][2], accS[j][3]));
        }
        tm0 = fmaxf(tm0, __shfl_xor_sync(0xffffffffu, tm0, 1));
        tm1 = fmaxf(tm1, __shfl_xor_sync(0xffffffffu, tm1, 1));
        tm0 = fmaxf(tm0, __shfl_xor_sync(0xffffffffu, tm0, 2));
        tm1 = fmaxf(tm1, __shfl_xor_sync(0xffffffffu, tm1, 2));

        const u32 vbase = kvb + KTB + voff;
        u32 vc[4], vn[4];
        ldsm_x4_t(vc, vbase);    // first V fragment overlaps the ALU below

        const float nm0 = fmaxf(m0, tm0);
        const float nm1 = fmaxf(m1, tm1);
        const float al0 = __expf(m0 - nm0);
        const float al1 = __expf(m1 - nm1);
        m0 = nm0; m1 = nm1;
        const float c0 = -nm0 * L2E;
        const float c1 = -nm1 * L2E;

#pragma unroll
        for (int j = 0; j < 8; ++j) {
            accO[j][0] *= al0; accO[j][1] *= al0;
            accO[j][2] *= al1; accO[j][3] *= al1;
        }
        accL[0] *= al0;
        accL[2] *= al1;

        // ---- PV: per kt convert to fp16 P, then MMAs with pipelined V fragments ----
#pragma unroll
        for (int idx = 0; idx < 16; ++idx) {
            const int kt = idx >> 2, q = idx & 3;
            u32 ah[4];
            if (q == 0) {
                ah[0] = ex2_f16x2(cvt_f16x2(fmaf(accS[2 * kt][0], L2E, c0),
                                            fmaf(accS[2 * kt][1], L2E, c0)));
                ah[1] = ex2_f16x2(cvt_f16x2(fmaf(accS[2 * kt][2], L2E, c1),
                                            fmaf(accS[2 * kt][3], L2E, c1)));
                ah[2] = ex2_f16x2(cvt_f16x2(fmaf(accS[2 * kt + 1][0], L2E, c0),
                                            fmaf(accS[2 * kt + 1][1], L2E, c0)));
                ah[3] = ex2_f16x2(cvt_f16x2(fmaf(accS[2 * kt + 1][2], L2E, c1),
                                            fmaf(accS[2 * kt + 1][3], L2E, c1)));
                // stash in accS slots (dead after conversion) so ah persists across q
                accS[2 * kt][0] = __uint_as_float(ah[0]);
                accS[2 * kt][1] = __uint_as_float(ah[1]);
                accS[2 * kt][2] = __uint_as_float(ah[2]);
                accS[2 * kt][3] = __uint_as_float(ah[3]);
                mma_fp16(accL, ah, ONE2, ONE2);   // row sums via tensor pipe
            } else {
                ah[0] = __float_as_uint(accS[2 * kt][0]);
                ah[1] = __float_as_uint(accS[2 * kt][1]);
                ah[2] = __float_as_uint(accS[2 * kt][2]);
                ah[3] = __float_as_uint(accS[2 * kt][3]);
            }
            if (idx < 15) {
                const int n = idx + 1;
                ldsm_x4_t(vn, vbase + (n >> 2) * (16 * PITCH) + (n & 3) * 32);
            }
            mma_fp16(accO[2 * q],     ah, vc[0], vc[1]);
            mma_fp16(accO[2 * q + 1], ah, vc[2], vc[3]);
            vc[0] = vn[0]; vc[1] = vn[1]; vc[2] = vn[2]; vc[3] = vn[3];
        }

        // ---- release the slot ----
        MBARRIER_ARRIVE(MB_EMPTY(cstage));
        if (++cstage == NSLOT) { cstage = 0; cphase ^= 1; }
    }

    // ---- epilogue: l exact from the ones-MMA ----
    const float inv0 = 1.f / accL[0];
    const float inv1 = 1.f / accL[2];

    const int row0 = mbase + 16 * w + (lane >> 2);
    float* o0 = O + (((size_t)b * Ln + row0) * Hn + h) * Dn + (lane & 3) * 2;
    float* o1 = o0 + (size_t)8 * Hn * Dn;
#pragma unroll
    for (int j = 0; j < 8; ++j) {
        *(float2*)(o0 + 8 * j) = make_float2(accO[j][0] * inv0, accO[j][1] * inv0);
        *(float2*)(o1 + 8 * j) = make_float2(accO[j][2] * inv1, accO[j][3] * inv1);
    }
}

// ---------------- launch ----------------
extern "C" void kernel_launch(void* const* d_in, const int* in_sizes, int n_in,
                              void* d_out, int out_size) {
    const float* Q = (const float*)d_in[0];
    const float* K = (const float*)d_in[1];
    const float* V = (const float*)d_in[2];
    float* O = (float*)d_out;

    pack_all<<<dim3(8192, 3), 256>>>(Q, K, V);

    cudaFuncSetAttribute(fattn_mma, cudaFuncAttributeMaxDynamicSharedMemorySize, SMEM_BYTES);
    fattn_mma<<<dim3(Ln / BM, Bn * Hn), NT, SMEM_BYTES>>>(O);
}